// round 15
// baseline (speedup 1.0000x reference)
#include <cuda_runtime.h>
#include <cuda_fp16.h>
#include <stdint.h>

#define NCTA 128
#define NTHR 256
#define Bsz  256
#define Tn   1024
#define Hn   512
#define APAD 520      // padded smem row (halfs): 260 words % 32 == 4 -> conflict-free
#define XBS  36       // sXB row stride (floats)

#define OFF_FEAT 1
#define OFF_INP  (1 + Bsz*Hn)
#define OFF_OUT  (1 + Bsz*Hn + Bsz*Tn)

// smem byte offsets
#define SO_W   0         // half sW[104][APAD] = 108160  (96 gate rows + Wout row + 7 zero)
#define SO_A   108160    // half sA[32][APAD]  = 33280
#define SO_P   141440    // float sP[7][32]    = 896 (pad 1024)
#define SO_XB  142464    // float sXB[32][XBS] = 4608
#define SO_X   147072    // float sX[32]
#define SO_SEQ 147200    // int sSeq[32]
#define SO_L   147328    // float sL; int sCnt
#define SO_BAR 147344    // unsigned sBar[2]
#define SMEMSZ 147456

__device__ __half   g_hh[2][Bsz][Hn];   // fp16 hidden state (MMA feed)
__device__ float    g_loss;
__device__ unsigned g_done;
__device__ unsigned g_cnt0, g_gen0;     // one-shot global barrier (monotonic)
__device__ unsigned g_cnt8[8][64];      // per-batch-group arrival counters (256B apart)

__device__ __forceinline__ float sigf(float x){ return __fdividef(1.f, 1.f + __expf(-x)); }
__device__ __forceinline__ float tanhf_(float x){ float e = __expf(2.f*x); return 1.f - __fdividef(2.f, e + 1.f); }
__device__ __forceinline__ uint32_t smaddr(const void* p){ return (uint32_t)__cvta_generic_to_shared(p); }

__device__ __forceinline__ unsigned ld_acq(const unsigned* p){
    unsigned v;
    asm volatile("ld.acquire.gpu.global.u32 %0,[%1];" : "=r"(v) : "l"(p) : "memory");
    return v;
}
__device__ __forceinline__ void st_rel(unsigned* p, unsigned v){
    asm volatile("st.release.gpu.global.u32 [%0],%1;" :: "l"(p), "r"(v) : "memory");
}
__device__ __forceinline__ unsigned atom_rel_add(unsigned* p, unsigned v){
    unsigned old;
    asm volatile("atom.release.gpu.global.add.u32 %0,[%1],%2;" : "=r"(old) : "l"(p), "r"(v) : "memory");
    return old;
}
__device__ __forceinline__ void red_rel_add(unsigned* p, unsigned v){
    asm volatile("red.release.gpu.global.add.u32 [%0],%1;" :: "l"(p), "r"(v) : "memory");
}

// One-shot monotonic counting barrier (init only).
__device__ __forceinline__ void barG(unsigned* cnt, unsigned* gen, unsigned ph, unsigned n){
    __syncthreads();
    if (threadIdx.x == 0){
        unsigned old = atom_rel_add(cnt, 1u);
        if (old == ph * n - 1u){
            st_rel(gen, ph);
        } else {
            while ((int)(ld_acq(gen) - ph) < 0) __nanosleep(32);
        }
    }
    __syncthreads();
}

// Single-hop step barrier: fire-and-forget arrival, dual-issue poll on the counter.
__device__ __forceinline__ void barN_red(unsigned* cnt, unsigned tgt){
    __syncthreads();
    if (threadIdx.x == 0){
        red_rel_add(cnt, 1u);
        for (;;){
            unsigned v1 = ld_acq(cnt);
            unsigned v2 = ld_acq(cnt);
            if ((int)(v1 - tgt) >= 0 || (int)(v2 - tgt) >= 0) break;
        }
    }
    __syncthreads();
}

__device__ __forceinline__ void mma16816(float* c, const uint32_t* a, uint32_t b0, uint32_t b1){
    asm volatile("mma.sync.aligned.m16n8k16.row.col.f32.f16.f16.f32 "
                 "{%0,%1,%2,%3},{%4,%5,%6,%7},{%8,%9},{%0,%1,%2,%3};\n"
                 : "+f"(c[0]), "+f"(c[1]), "+f"(c[2]), "+f"(c[3])
                 : "r"(a[0]), "r"(a[1]), "r"(a[2]), "r"(a[3]), "r"(b0), "r"(b1));
}
__device__ __forceinline__ void ldsm4(uint32_t* r, uint32_t addr){
    asm volatile("ldmatrix.sync.aligned.m8n8.x4.shared.b16 {%0,%1,%2,%3},[%4];"
                 : "=r"(r[0]),"=r"(r[1]),"=r"(r[2]),"=r"(r[3]) : "r"(addr));
}
__device__ __forceinline__ void ldsm2(uint32_t* r, uint32_t addr){
    asm volatile("ldmatrix.sync.aligned.m8n8.x2.shared.b16 {%0,%1},[%2];"
                 : "=r"(r[0]),"=r"(r[1]) : "r"(addr));
}

// Load this phase's B fragments into registers ONCE (identical ldmatrix addresses
// to the per-step loads they replace -> bit-identical values).
__device__ __forceinline__ void load_B_frags(const __half* sW, int tid,
                                             uint32_t (&wb)[32][4], uint32_t (&wc)[32][2]){
    int lane = tid & 31, warp = tid >> 5;
    int wn = warp & 3;
    int grp = lane >> 3, l7 = lane & 7, l15 = lane & 15;
    uint32_t aB = smaddr(sW + (wn*24 + (grp >> 1)*8 + l7)*APAD + (grp & 1)*8);
    uint32_t aC = smaddr(sW + (wn*24 + 16 + (l15 & 7))*APAD + (l15 >> 3)*8);
    #pragma unroll
    for (int kt = 0; kt < 32; kt++){
        ldsm4(wb[kt], aB);
        ldsm2(wc[kt], aC);
        aB += 32; aC += 32;
    }
}

// A = h (M=32 batch) from smem; B resident in registers. K=512 fully unrolled.
// A is double-buffered so its LDSM latency overlaps the MMAs.
template<bool WY>
__device__ __forceinline__ void mma_step(const uint32_t (&wb)[32][4], const uint32_t (&wc)[32][2],
                                         const __half* sW, const __half* sA, int tid,
                                         float (&acc)[3][4], float (&accY)[4]){
    int lane = tid & 31, warp = tid >> 5;
    int wm = warp >> 2, wn = warp & 3;
    int grp = lane >> 3, l7 = lane & 7, l15 = lane & 15;

    int rowA = wm*16 + (grp & 1)*8 + l7;
    uint32_t aA = smaddr(sA + rowA*APAD + (grp >> 1)*8);
    uint32_t aY = smaddr(sW + (96 + (l15 & 7))*APAD + (l15 >> 3)*8);
    const bool doY = WY && (wn == 0);

    #pragma unroll
    for (int nt = 0; nt < 3; nt++)
        #pragma unroll
        for (int i = 0; i < 4; i++) acc[nt][i] = 0.f;
    #pragma unroll
    for (int i = 0; i < 4; i++) accY[i] = 0.f;

    uint32_t fa[2][4];
    ldsm4(fa[0], aA);
    #pragma unroll
    for (int kt = 0; kt < 32; kt++){
        int cur = kt & 1, nx = cur ^ 1;
        if (kt < 31){ aA += 32; ldsm4(fa[nx], aA); }
        mma16816(acc[0], fa[cur], wb[kt][0], wb[kt][1]);
        mma16816(acc[1], fa[cur], wb[kt][2], wb[kt][3]);
        mma16816(acc[2], fa[cur], wc[kt][0], wc[kt][1]);
        if (doY){
            uint32_t fy[2];
            ldsm2(fy, aY); aY += 32;
            mma16816(accY, fa[cur], fy[0], fy[1]);
        }
    }
}

// gate-interleaved rows: j = wn*24 + gate*8 + uu  <->  Whh row gate*Hn + U0 + wn*8 + uu
__device__ __forceinline__ void load_phase_weights(const float* Wih, const float* Whh,
                                                   const float* bih, const float* bhh,
                                                   const float* Wout,
                                                   __half* sW, float* sP, int tid, int U0){
    for (int q = 0; q < 48; q++){
        int li = q*256 + tid;
        int j = li >> 7, c4 = li & 127;
        int wn = j / 24, rem = j % 24;
        int grow = (rem >> 3) * Hn + U0 + wn*8 + (rem & 7);
        float4 v = *(const float4*)&Whh[(size_t)grow * Hn + c4*4];
        *(__half2*)&sW[j*APAD + c4*4]     = __floats2half2_rn(v.x, v.y);
        *(__half2*)&sW[j*APAD + c4*4 + 2] = __floats2half2_rn(v.z, v.w);
    }
    for (int q = 0; q < 4; q++){
        int li = q*256 + tid;
        int j = 96 + (li >> 7), c4 = li & 127;
        __half2 z = __floats2half2_rn(0.f, 0.f);
        __half2 h0 = z, h1 = z;
        if (j == 96){
            float4 v = *(const float4*)&Wout[c4*4];
            h0 = __floats2half2_rn(v.x, v.y);
            h1 = __floats2half2_rn(v.z, v.w);
        }
        *(__half2*)&sW[j*APAD + c4*4]     = h0;
        *(__half2*)&sW[j*APAD + c4*4 + 2] = h1;
    }
    if (tid < 32){
        int u = tid, gu = U0 + u;
        sP[u]       = Wih[gu];
        sP[32 + u]  = Wih[Hn + gu];
        sP[64 + u]  = Wih[2*Hn + gu];
        sP[96 + u]  = bih[gu] + bhh[gu];
        sP[128 + u] = bih[Hn + gu] + bhh[Hn + gu];
        sP[160 + u] = bih[2*Hn + gu];
        sP[192 + u] = bhh[2*Hn + gu];
    }
}

// copy 32x512 halfs from g_hh[cur][B0..] into sA (LDG.128 -> STS.128)
__device__ __forceinline__ void load_A(int cur, int B0, __half* sA, int tid){
    const uint4* src = (const uint4*)&g_hh[cur][B0][0];   // row stride = 64 uint4
    #pragma unroll
    for (int q = 0; q < 8; q++){
        int li = q*256 + tid;
        int row = li >> 6, c = li & 63;
        uint4 v = __ldcg(src + row*64 + c);
        *(uint4*)&sA[row*APAD + c*8] = v;
    }
}

// Epilogue straight from mma fragments; thread owns 4 (b,u) pairs (stable across steps).
__device__ __forceinline__ void epilogue_frag(const float (&acc)[3][4], const float* sP,
        const float* xb, int xstride, const int* sSeq, float* hreg,
        int tid, int B0, int U0, int nxt, int t, bool enc){
    int lane = tid & 31, warp = tid >> 5;
    int wm = warp >> 2, wn = warp & 3;
    int g = lane >> 2, tg2 = (lane & 3)*2;
    int u0 = wn*8 + tg2;
    float2 wir = *(const float2*)&sP[u0];
    float2 wiz = *(const float2*)&sP[32+u0];
    float2 win = *(const float2*)&sP[64+u0];
    float2 br  = *(const float2*)&sP[96+u0];
    float2 bz  = *(const float2*)&sP[128+u0];
    float2 bin = *(const float2*)&sP[160+u0];
    float2 bhn = *(const float2*)&sP[192+u0];
    #pragma unroll
    for (int j = 0; j < 2; j++){
        int b = wm*16 + g + j*8;
        float x = xb[b*xstride];
        bool valid = enc ? (t < sSeq[b]) : true;
        float r0 = sigf(x*wir.x + br.x + acc[0][j*2]);
        float z0 = sigf(x*wiz.x + bz.x + acc[1][j*2]);
        float n0 = tanhf_(x*win.x + bin.x + r0*(acc[2][j*2] + bhn.x));
        float h0 = (1.f - z0)*n0 + z0*hreg[j*2];
        if (valid) hreg[j*2] = h0;
        float r1 = sigf(x*wir.y + br.y + acc[0][j*2+1]);
        float z1 = sigf(x*wiz.y + bz.y + acc[1][j*2+1]);
        float n1 = tanhf_(x*win.y + bin.y + r1*(acc[2][j*2+1] + bhn.y));
        float h1 = (1.f - z1)*n1 + z1*hreg[j*2+1];
        if (valid) hreg[j*2+1] = h1;
        *(__half2*)&g_hh[nxt][B0 + b][U0 + u0] = __floats2half2_rn(hreg[j*2], hreg[j*2+1]);
    }
}

__global__ __launch_bounds__(NTHR, 1)
void gru_ae_kernel(const float* __restrict__ input, const int* __restrict__ seq,
                   const float* __restrict__ eWih, const float* __restrict__ eWhh,
                   const float* __restrict__ ebih, const float* __restrict__ ebhh,
                   const float* __restrict__ dWih, const float* __restrict__ dWhh,
                   const float* __restrict__ dbih, const float* __restrict__ dbhh,
                   const float* __restrict__ Wout, const float* __restrict__ bout,
                   float* __restrict__ out){
    extern __shared__ __align__(16) char sm[];
    __half* sW  = (__half*)(sm + SO_W);
    __half* sA  = (__half*)(sm + SO_A);
    float* sP   = (float*)(sm + SO_P);
    float* sXB  = (float*)(sm + SO_XB);
    float* sX   = (float*)(sm + SO_X);
    int*   sSeq = (int*)(sm + SO_SEQ);
    float* sL   = (float*)(sm + SO_L);
    int*   sCnt = (int*)(sm + SO_L + 4);
    unsigned* sBar = (unsigned*)(sm + SO_BAR);

    int tid = threadIdx.x;
    int lane = tid & 31, warp = tid >> 5;
    int wm = warp >> 2, wn = warp & 3;
    int s = blockIdx.x >> 3, bg = blockIdx.x & 7;
    int B0 = bg * 32, U0 = s * 32;
    unsigned* cnt = &g_cnt8[bg][0];
    float bo = bout[0];
    float hreg[4] = {0.f, 0.f, 0.f, 0.f};
    float acc[3][4], accY[4];
    uint32_t wb[32][4], wc[32][2];   // phase-resident B fragments

    if (blockIdx.x == 0 && tid == 0){ g_loss = 0.f; g_done = 0u; }
    // Persistent bases, read pre-arrival (quiescent: arrivals this launch start after barG).
    if (tid == 0){ sBar[0] = g_gen0; sBar[1] = *(volatile unsigned*)cnt; }

    // zero own slice of g_hh[0] (fragment-keyed ownership)
    {
        int g = lane >> 2, tg2 = (lane & 3)*2;
        int u0 = U0 + wn*8 + tg2;
        __half2 z2 = __floats2half2_rn(0.f, 0.f);
        *(__half2*)&g_hh[0][B0 + wm*16 + g][u0]     = z2;
        *(__half2*)&g_hh[0][B0 + wm*16 + g + 8][u0] = z2;
    }
    if (tid < 32) sSeq[tid] = seq[B0 + tid];
    if (tid == 0){ sL[0] = 0.f; sCnt[0] = 0; }
    __syncthreads();
    unsigned S0  = sBar[0];
    unsigned tgt = sBar[1];
    {
        int v = seq[tid];
        #pragma unroll
        for (int o = 16; o > 0; o >>= 1) v += __shfl_down_sync(0xffffffffu, v, o);
        if ((tid & 31) == 0) atomicAdd(sCnt, v);
    }
    load_phase_weights(eWih, eWhh, ebih, ebhh, Wout, sW, sP, tid, U0);
    barG(&g_cnt0, &g_gen0, S0 + 1u, NCTA);   // h[0] zeros + loss reset visible chip-wide
    load_B_frags(sW, tid, wb, wc);

    // ---------------- Encoder ----------------
    #pragma unroll 1
    for (int t = 0; t < Tn; t++){
        int nxt = (t & 1) ^ 1;
        load_A(t & 1, B0, sA, tid);
        if ((t & 31) == 0){
            int row = tid >> 3, c4 = (tid & 7) * 4;
            float4 v = *(const float4*)&input[(size_t)(B0 + row) * Tn + t + c4];
            *(float4*)&sXB[row*XBS + c4] = v;
        }
        __syncthreads();
        mma_step<false>(wb, wc, sW, sA, tid, acc, accY);
        epilogue_frag(acc, sP, sXB + (t & 31), XBS, sSeq, hreg, tid, B0, U0, nxt, t, true);
        tgt += 16u;
        barN_red(cnt, tgt);
    }
    // features = h_final (registers, fragment-keyed)
    {
        int g = lane >> 2, tg2 = (lane & 3)*2;
        int u0 = U0 + wn*8 + tg2;
        #pragma unroll
        for (int j = 0; j < 2; j++){
            int b = B0 + wm*16 + g + j*8;
            out[OFF_FEAT + (size_t)b * Hn + u0]     = hreg[j*2];
            out[OFF_FEAT + (size_t)b * Hn + u0 + 1] = hreg[j*2+1];
        }
    }
    __syncthreads();   // all reads of encoder sW done (frags are in regs)
    load_phase_weights(dWih, dWhh, dbih, dbhh, Wout, sW, sP, tid, U0);
    __syncthreads();
    load_B_frags(sW, tid, wb, wc);

    // ---------------- Decoder ----------------
    // Output/loss stores distributed: stripe s owns batch rows 2s and 2s+1 (uniform work).
    float loss_acc = 0.f;
    #pragma unroll 1
    for (int t = 0; t < Tn; t++){
        int nxt = (t & 1) ^ 1;
        load_A(t & 1, B0, sA, tid);
        __syncthreads();
        mma_step<true>(wb, wc, sW, sA, tid, acc, accY);
        if (wn == 0 && (lane & 3) == 0){
            int g = lane >> 2;
            #pragma unroll
            for (int j = 0; j < 2; j++){
                int b = wm*16 + g + j*8;
                float yv = accY[j*2] + bo;      // y from pre-update h == y_{t-1}
                sX[b] = (t == 0) ? 0.f : yv;
                if (t > 0 && (b >> 1) == s){
                    out[OFF_OUT + (size_t)(B0 + b) * Tn + (t - 1)] = yv;
                    if ((t - 1) < sSeq[b]){
                        float d = __ldg(&input[(size_t)(B0 + b) * Tn + (t - 1)]) - yv;
                        loss_acc += d * d;
                    }
                }
            }
        }
        __syncthreads();
        epilogue_frag(acc, sP, sX, 1, sSeq, hreg, tid, B0, U0, nxt, t, false);
        tgt += 16u;
        barN_red(cnt, tgt);
    }
    // final y_1023 from h_1024 (parity 0)
    load_A(0, B0, sA, tid);
    __syncthreads();
    mma_step<true>(wb, wc, sW, sA, tid, acc, accY);
    if (wn == 0 && (lane & 3) == 0){
        int g = lane >> 2;
        #pragma unroll
        for (int j = 0; j < 2; j++){
            int b = wm*16 + g + j*8;
            if ((b >> 1) == s){
                float yv = accY[j*2] + bo;
                out[OFF_OUT + (size_t)(B0 + b) * Tn + (Tn - 1)] = yv;
                if ((Tn - 1) < sSeq[b]){
                    float d = __ldg(&input[(size_t)(B0 + b) * Tn + (Tn - 1)]) - yv;
                    loss_acc += d * d;
                }
            }
        }
    }
    __syncthreads();
    if (wn == 0 && (lane & 3) == 0) atomicAdd(sL, loss_acc);
    __syncthreads();
    if (tid == 0){
        atomicAdd(&g_loss, sL[0]);
        atom_rel_add(&g_done, 1u);
    }
    if (blockIdx.x == 0 && tid == 0){
        while (ld_acq(&g_done) < (unsigned)NCTA) __nanosleep(128);
        out[0] = g_loss / (float)sCnt[0];
    }
}

extern "C" void kernel_launch(void* const* d_in, const int* in_sizes, int n_in,
                              void* d_out, int out_size){
    (void)in_sizes; (void)n_in; (void)out_size;
    const float* input = (const float*)d_in[0];
    const int*   seq   = (const int*)d_in[1];
    const float* eWih  = (const float*)d_in[2];
    const float* eWhh  = (const float*)d_in[3];
    const float* ebih  = (const float*)d_in[4];
    const float* ebhh  = (const float*)d_in[5];
    const float* dWih  = (const float*)d_in[6];
    const float* dWhh  = (const float*)d_in[7];
    const float* dbih  = (const float*)d_in[8];
    const float* dbhh  = (const float*)d_in[9];
    const float* Wout  = (const float*)d_in[10];
    const float* bo    = (const float*)d_in[11];
    float* out = (float*)d_out;

    cudaFuncSetAttribute(gru_ae_kernel, cudaFuncAttributeMaxDynamicSharedMemorySize, SMEMSZ);

    cudaMemcpyAsync(out + OFF_INP, input, (size_t)Bsz * Tn * sizeof(float),
                    cudaMemcpyDeviceToDevice, 0);
    gru_ae_kernel<<<NCTA, NTHR, SMEMSZ, 0>>>(input, seq, eWih, eWhh, ebih, ebhh,
                                             dWih, dWhh, dbih, dbhh, Wout, bo, out);
}

// round 16
// speedup vs baseline: 1.1071x; 1.1071x over previous
#include <cuda_runtime.h>
#include <cuda_fp16.h>
#include <stdint.h>

#define NCTA 128
#define NTHR 256
#define Bsz  256
#define Tn   1024
#define Hn   512
#define APAD 520      // padded smem row (halfs): 260 words % 32 == 4 -> conflict-free
#define XBS  36       // sXB row stride (floats)

#define OFF_FEAT 1
#define OFF_INP  (1 + Bsz*Hn)
#define OFF_OUT  (1 + Bsz*Hn + Bsz*Tn)

// smem byte offsets
#define SO_W   0         // half sW[104][APAD] = 108160  (96 gate rows + Wout row + 7 zero)
#define SO_A   108160    // half sA[32][APAD]  = 33280
#define SO_P   141440    // float sP[7][32]    = 896 (pad 1024)
#define SO_XB  142464    // float sXB[32][XBS] = 4608
#define SO_X   147072    // float sX[32]
#define SO_SEQ 147200    // int sSeq[32]
#define SO_L   147328    // float sL; int sCnt
#define SO_BAR 147344    // unsigned sBar[2]
#define SMEMSZ 147456

__device__ __half   g_hh[2][Bsz][Hn];   // fp16 hidden state (MMA feed)
__device__ float    g_loss;
__device__ unsigned g_done;
__device__ unsigned g_cnt0, g_gen0;     // one-shot global barrier (monotonic)
__device__ unsigned g_cnt8[8][64];      // per-batch-group arrival counters (256B apart)

__device__ __forceinline__ float sigf(float x){ return __fdividef(1.f, 1.f + __expf(-x)); }
__device__ __forceinline__ float tanhf_(float x){ float e = __expf(2.f*x); return 1.f - __fdividef(2.f, e + 1.f); }
__device__ __forceinline__ uint32_t smaddr(const void* p){ return (uint32_t)__cvta_generic_to_shared(p); }

__device__ __forceinline__ unsigned ld_acq(const unsigned* p){
    unsigned v;
    asm volatile("ld.acquire.gpu.global.u32 %0,[%1];" : "=r"(v) : "l"(p) : "memory");
    return v;
}
__device__ __forceinline__ void st_rel(unsigned* p, unsigned v){
    asm volatile("st.release.gpu.global.u32 [%0],%1;" :: "l"(p), "r"(v) : "memory");
}
__device__ __forceinline__ unsigned atom_rel_add(unsigned* p, unsigned v){
    unsigned old;
    asm volatile("atom.release.gpu.global.add.u32 %0,[%1],%2;" : "=r"(old) : "l"(p), "r"(v) : "memory");
    return old;
}
__device__ __forceinline__ void red_rel_add(unsigned* p, unsigned v){
    asm volatile("red.release.gpu.global.add.u32 [%0],%1;" :: "l"(p), "r"(v) : "memory");
}

// One-shot monotonic counting barrier (init only).
__device__ __forceinline__ void barG(unsigned* cnt, unsigned* gen, unsigned ph, unsigned n){
    __syncthreads();
    if (threadIdx.x == 0){
        unsigned old = atom_rel_add(cnt, 1u);
        if (old == ph * n - 1u){
            st_rel(gen, ph);
        } else {
            while ((int)(ld_acq(gen) - ph) < 0) __nanosleep(32);
        }
    }
    __syncthreads();
}

// Single-hop step barrier: fire-and-forget arrival, poll the counter itself.
__device__ __forceinline__ void barN_red(unsigned* cnt, unsigned tgt){
    __syncthreads();
    if (threadIdx.x == 0){
        red_rel_add(cnt, 1u);
        while ((int)(ld_acq(cnt) - tgt) < 0) { }
    }
    __syncthreads();
}

__device__ __forceinline__ void mma16816(float* c, const uint32_t* a, uint32_t b0, uint32_t b1){
    asm volatile("mma.sync.aligned.m16n8k16.row.col.f32.f16.f16.f32 "
                 "{%0,%1,%2,%3},{%4,%5,%6,%7},{%8,%9},{%0,%1,%2,%3};\n"
                 : "+f"(c[0]), "+f"(c[1]), "+f"(c[2]), "+f"(c[3])
                 : "r"(a[0]), "r"(a[1]), "r"(a[2]), "r"(a[3]), "r"(b0), "r"(b1));
}
__device__ __forceinline__ void ldsm4(uint32_t* r, uint32_t addr){
    asm volatile("ldmatrix.sync.aligned.m8n8.x4.shared.b16 {%0,%1,%2,%3},[%4];"
                 : "=r"(r[0]),"=r"(r[1]),"=r"(r[2]),"=r"(r[3]) : "r"(addr));
}
__device__ __forceinline__ void ldsm2(uint32_t* r, uint32_t addr){
    asm volatile("ldmatrix.sync.aligned.m8n8.x2.shared.b16 {%0,%1},[%2];"
                 : "=r"(r[0]),"=r"(r[1]) : "r"(addr));
}

// Load this phase's B fragments into registers ONCE (identical ldmatrix addresses
// to the per-step loads they replace -> bit-identical values).
__device__ __forceinline__ void load_B_frags(const __half* sW, int tid,
                                             uint32_t (&wb)[32][4], uint32_t (&wc)[32][2]){
    int lane = tid & 31, warp = tid >> 5;
    int wn = warp & 3;
    int grp = lane >> 3, l7 = lane & 7, l15 = lane & 15;
    uint32_t aB = smaddr(sW + (wn*24 + (grp >> 1)*8 + l7)*APAD + (grp & 1)*8);
    uint32_t aC = smaddr(sW + (wn*24 + 16 + (l15 & 7))*APAD + (l15 >> 3)*8);
    #pragma unroll
    for (int kt = 0; kt < 32; kt++){
        ldsm4(wb[kt], aB);
        ldsm2(wc[kt], aC);
        aB += 32; aC += 32;
    }
}

// A = h (M=32 batch) from smem; B resident in registers. K=512 fully unrolled.
// A is double-buffered so its LDSM latency overlaps the MMAs.
template<bool WY>
__device__ __forceinline__ void mma_step(const uint32_t (&wb)[32][4], const uint32_t (&wc)[32][2],
                                         const __half* sW, const __half* sA, int tid,
                                         float (&acc)[3][4], float (&accY)[4]){
    int lane = tid & 31, warp = tid >> 5;
    int wm = warp >> 2, wn = warp & 3;
    int grp = lane >> 3, l7 = lane & 7, l15 = lane & 15;

    int rowA = wm*16 + (grp & 1)*8 + l7;
    uint32_t aA = smaddr(sA + rowA*APAD + (grp >> 1)*8);
    uint32_t aY = smaddr(sW + (96 + (l15 & 7))*APAD + (l15 >> 3)*8);
    const bool doY = WY && (wn == 0);

    #pragma unroll
    for (int nt = 0; nt < 3; nt++)
        #pragma unroll
        for (int i = 0; i < 4; i++) acc[nt][i] = 0.f;
    #pragma unroll
    for (int i = 0; i < 4; i++) accY[i] = 0.f;

    uint32_t fa[2][4];
    ldsm4(fa[0], aA);
    #pragma unroll
    for (int kt = 0; kt < 32; kt++){
        int cur = kt & 1, nx = cur ^ 1;
        if (kt < 31){ aA += 32; ldsm4(fa[nx], aA); }
        mma16816(acc[0], fa[cur], wb[kt][0], wb[kt][1]);
        mma16816(acc[1], fa[cur], wb[kt][2], wb[kt][3]);
        mma16816(acc[2], fa[cur], wc[kt][0], wc[kt][1]);
        if (doY){
            uint32_t fy[2];
            ldsm2(fy, aY); aY += 32;
            mma16816(accY, fa[cur], fy[0], fy[1]);
        }
    }
}

// gate-interleaved rows: j = wn*24 + gate*8 + uu  <->  Whh row gate*Hn + U0 + wn*8 + uu
__device__ __forceinline__ void load_phase_weights(const float* Wih, const float* Whh,
                                                   const float* bih, const float* bhh,
                                                   const float* Wout,
                                                   __half* sW, float* sP, int tid, int U0){
    for (int q = 0; q < 48; q++){
        int li = q*256 + tid;
        int j = li >> 7, c4 = li & 127;
        int wn = j / 24, rem = j % 24;
        int grow = (rem >> 3) * Hn + U0 + wn*8 + (rem & 7);
        float4 v = *(const float4*)&Whh[(size_t)grow * Hn + c4*4];
        *(__half2*)&sW[j*APAD + c4*4]     = __floats2half2_rn(v.x, v.y);
        *(__half2*)&sW[j*APAD + c4*4 + 2] = __floats2half2_rn(v.z, v.w);
    }
    for (int q = 0; q < 4; q++){
        int li = q*256 + tid;
        int j = 96 + (li >> 7), c4 = li & 127;
        __half2 z = __floats2half2_rn(0.f, 0.f);
        __half2 h0 = z, h1 = z;
        if (j == 96){
            float4 v = *(const float4*)&Wout[c4*4];
            h0 = __floats2half2_rn(v.x, v.y);
            h1 = __floats2half2_rn(v.z, v.w);
        }
        *(__half2*)&sW[j*APAD + c4*4]     = h0;
        *(__half2*)&sW[j*APAD + c4*4 + 2] = h1;
    }
    if (tid < 32){
        int u = tid, gu = U0 + u;
        sP[u]       = Wih[gu];
        sP[32 + u]  = Wih[Hn + gu];
        sP[64 + u]  = Wih[2*Hn + gu];
        sP[96 + u]  = bih[gu] + bhh[gu];
        sP[128 + u] = bih[Hn + gu] + bhh[Hn + gu];
        sP[160 + u] = bih[2*Hn + gu];
        sP[192 + u] = bhh[2*Hn + gu];
    }
}

// copy 32x512 halfs from g_hh[cur][B0..] into sA (LDG.128 -> STS.128)
__device__ __forceinline__ void load_A(int cur, int B0, __half* sA, int tid){
    const uint4* src = (const uint4*)&g_hh[cur][B0][0];   // row stride = 64 uint4
    #pragma unroll
    for (int q = 0; q < 8; q++){
        int li = q*256 + tid;
        int row = li >> 6, c = li & 63;
        uint4 v = __ldcg(src + row*64 + c);
        *(uint4*)&sA[row*APAD + c*8] = v;
    }
}

// Epilogue straight from mma fragments; thread owns 4 (b,u) pairs (stable across steps).
__device__ __forceinline__ void epilogue_frag(const float (&acc)[3][4], const float* sP,
        const float* xb, int xstride, const int* sSeq, float* hreg,
        int tid, int B0, int U0, int nxt, int t, bool enc){
    int lane = tid & 31, warp = tid >> 5;
    int wm = warp >> 2, wn = warp & 3;
    int g = lane >> 2, tg2 = (lane & 3)*2;
    int u0 = wn*8 + tg2;
    float2 wir = *(const float2*)&sP[u0];
    float2 wiz = *(const float2*)&sP[32+u0];
    float2 win = *(const float2*)&sP[64+u0];
    float2 br  = *(const float2*)&sP[96+u0];
    float2 bz  = *(const float2*)&sP[128+u0];
    float2 bin = *(const float2*)&sP[160+u0];
    float2 bhn = *(const float2*)&sP[192+u0];
    #pragma unroll
    for (int j = 0; j < 2; j++){
        int b = wm*16 + g + j*8;
        float x = xb[b*xstride];
        bool valid = enc ? (t < sSeq[b]) : true;
        float r0 = sigf(x*wir.x + br.x + acc[0][j*2]);
        float z0 = sigf(x*wiz.x + bz.x + acc[1][j*2]);
        float n0 = tanhf_(x*win.x + bin.x + r0*(acc[2][j*2] + bhn.x));
        float h0 = (1.f - z0)*n0 + z0*hreg[j*2];
        if (valid) hreg[j*2] = h0;
        float r1 = sigf(x*wir.y + br.y + acc[0][j*2+1]);
        float z1 = sigf(x*wiz.y + bz.y + acc[1][j*2+1]);
        float n1 = tanhf_(x*win.y + bin.y + r1*(acc[2][j*2+1] + bhn.y));
        float h1 = (1.f - z1)*n1 + z1*hreg[j*2+1];
        if (valid) hreg[j*2+1] = h1;
        *(__half2*)&g_hh[nxt][B0 + b][U0 + u0] = __floats2half2_rn(hreg[j*2], hreg[j*2+1]);
    }
}

__global__ __launch_bounds__(NTHR, 1)
void gru_ae_kernel(const float* __restrict__ input, const int* __restrict__ seq,
                   const float* __restrict__ eWih, const float* __restrict__ eWhh,
                   const float* __restrict__ ebih, const float* __restrict__ ebhh,
                   const float* __restrict__ dWih, const float* __restrict__ dWhh,
                   const float* __restrict__ dbih, const float* __restrict__ dbhh,
                   const float* __restrict__ Wout, const float* __restrict__ bout,
                   float* __restrict__ out){
    extern __shared__ __align__(16) char sm[];
    __half* sW  = (__half*)(sm + SO_W);
    __half* sA  = (__half*)(sm + SO_A);
    float* sP   = (float*)(sm + SO_P);
    float* sXB  = (float*)(sm + SO_XB);
    float* sX   = (float*)(sm + SO_X);
    int*   sSeq = (int*)(sm + SO_SEQ);
    float* sL   = (float*)(sm + SO_L);
    int*   sCnt = (int*)(sm + SO_L + 4);
    unsigned* sBar = (unsigned*)(sm + SO_BAR);

    int tid = threadIdx.x;
    int lane = tid & 31, warp = tid >> 5;
    int wm = warp >> 2, wn = warp & 3;
    int s = blockIdx.x >> 3, bg = blockIdx.x & 7;
    int B0 = bg * 32, U0 = s * 32;
    unsigned* cnt = &g_cnt8[bg][0];
    float bo = bout[0];
    float hreg[4] = {0.f, 0.f, 0.f, 0.f};
    float acc[3][4], accY[4];
    uint32_t wb[32][4], wc[32][2];   // phase-resident B fragments

    if (blockIdx.x == 0 && tid == 0){ g_loss = 0.f; g_done = 0u; }
    // Persistent bases, read pre-arrival (quiescent: arrivals this launch start after barG).
    if (tid == 0){ sBar[0] = g_gen0; sBar[1] = *(volatile unsigned*)cnt; }

    // zero own slice of g_hh[0] (fragment-keyed ownership)
    {
        int g = lane >> 2, tg2 = (lane & 3)*2;
        int u0 = U0 + wn*8 + tg2;
        __half2 z2 = __floats2half2_rn(0.f, 0.f);
        *(__half2*)&g_hh[0][B0 + wm*16 + g][u0]     = z2;
        *(__half2*)&g_hh[0][B0 + wm*16 + g + 8][u0] = z2;
    }
    if (tid < 32) sSeq[tid] = seq[B0 + tid];
    if (tid == 0){ sL[0] = 0.f; sCnt[0] = 0; }
    __syncthreads();
    unsigned S0  = sBar[0];
    unsigned tgt = sBar[1];
    {
        int v = seq[tid];
        #pragma unroll
        for (int o = 16; o > 0; o >>= 1) v += __shfl_down_sync(0xffffffffu, v, o);
        if ((tid & 31) == 0) atomicAdd(sCnt, v);
    }
    load_phase_weights(eWih, eWhh, ebih, ebhh, Wout, sW, sP, tid, U0);
    barG(&g_cnt0, &g_gen0, S0 + 1u, NCTA);   // h[0] zeros + loss reset visible chip-wide
    load_B_frags(sW, tid, wb, wc);

    // ---------------- Encoder ----------------
    #pragma unroll 1
    for (int t = 0; t < Tn; t++){
        int nxt = (t & 1) ^ 1;
        load_A(t & 1, B0, sA, tid);
        if ((t & 31) == 0){
            int row = tid >> 3, c4 = (tid & 7) * 4;
            float4 v = *(const float4*)&input[(size_t)(B0 + row) * Tn + t + c4];
            *(float4*)&sXB[row*XBS + c4] = v;
        }
        __syncthreads();
        mma_step<false>(wb, wc, sW, sA, tid, acc, accY);
        epilogue_frag(acc, sP, sXB + (t & 31), XBS, sSeq, hreg, tid, B0, U0, nxt, t, true);
        tgt += 16u;
        barN_red(cnt, tgt);
    }
    // features = h_final (registers, fragment-keyed)
    {
        int g = lane >> 2, tg2 = (lane & 3)*2;
        int u0 = U0 + wn*8 + tg2;
        #pragma unroll
        for (int j = 0; j < 2; j++){
            int b = B0 + wm*16 + g + j*8;
            out[OFF_FEAT + (size_t)b * Hn + u0]     = hreg[j*2];
            out[OFF_FEAT + (size_t)b * Hn + u0 + 1] = hreg[j*2+1];
        }
    }
    __syncthreads();   // all reads of encoder sW done (frags are in regs)
    load_phase_weights(dWih, dWhh, dbih, dbhh, Wout, sW, sP, tid, U0);
    __syncthreads();
    load_B_frags(sW, tid, wb, wc);

    // ---------------- Decoder ----------------
    // Global y/loss stores (s==0 CTAs) are deferred to AFTER the barrier arrival,
    // so they overlap the wait instead of making the s==0 CTA the straggler.
    float loss_acc = 0.f;
    #pragma unroll 1
    for (int t = 0; t < Tn; t++){
        int nxt = (t & 1) ^ 1;
        load_A(t & 1, B0, sA, tid);
        __syncthreads();
        mma_step<true>(wb, wc, sW, sA, tid, acc, accY);
        float yv0 = 0.f, yv1 = 0.f;
        if (wn == 0 && (lane & 3) == 0){
            int g = lane >> 2;
            yv0 = accY[0] + bo;   // row wm*16+g   (y from pre-update h == y_{t-1})
            yv1 = accY[2] + bo;   // row wm*16+g+8
            sX[wm*16 + g]     = (t == 0) ? 0.f : yv0;
            sX[wm*16 + g + 8] = (t == 0) ? 0.f : yv1;
        }
        __syncthreads();
        epilogue_frag(acc, sP, sX, 1, sSeq, hreg, tid, B0, U0, nxt, t, false);
        tgt += 16u;
        __syncthreads();
        if (tid == 0) red_rel_add(cnt, 1u);
        // deferred stores: overlap with the barrier wait
        if (wn == 0 && (lane & 3) == 0 && t > 0 && s == 0){
            int g = lane >> 2;
            int b0r = wm*16 + g, b1r = b0r + 8;
            out[OFF_OUT + (size_t)(B0 + b0r) * Tn + (t - 1)] = yv0;
            out[OFF_OUT + (size_t)(B0 + b1r) * Tn + (t - 1)] = yv1;
            if ((t - 1) < sSeq[b0r]){
                float d = __ldg(&input[(size_t)(B0 + b0r) * Tn + (t - 1)]) - yv0;
                loss_acc += d * d;
            }
            if ((t - 1) < sSeq[b1r]){
                float d = __ldg(&input[(size_t)(B0 + b1r) * Tn + (t - 1)]) - yv1;
                loss_acc += d * d;
            }
        }
        if (tid == 0){
            while ((int)(ld_acq(cnt) - tgt) < 0) { }
        }
        __syncthreads();
    }
    // final y_1023 from h_1024 (parity 0)
    load_A(0, B0, sA, tid);
    __syncthreads();
    mma_step<true>(wb, wc, sW, sA, tid, acc, accY);
    if (wn == 0 && (lane & 3) == 0 && s == 0){
        int g = lane >> 2;
        #pragma unroll
        for (int j = 0; j < 2; j++){
            int b = wm*16 + g + j*8;
            float yv = accY[j*2] + bo;
            out[OFF_OUT + (size_t)(B0 + b) * Tn + (Tn - 1)] = yv;
            if ((Tn - 1) < sSeq[b]){
                float d = __ldg(&input[(size_t)(B0 + b) * Tn + (Tn - 1)]) - yv;
                loss_acc += d * d;
            }
        }
    }
    __syncthreads();
    if (s == 0){
        if (wn == 0 && (lane & 3) == 0) atomicAdd(sL, loss_acc);
        __syncthreads();
        if (tid == 0){
            atomicAdd(&g_loss, sL[0]);
            atom_rel_add(&g_done, 1u);
        }
    }
    if (blockIdx.x == 0 && tid == 0){
        while (ld_acq(&g_done) < 8u) __nanosleep(128);
        out[0] = g_loss / (float)sCnt[0];
    }
}

extern "C" void kernel_launch(void* const* d_in, const int* in_sizes, int n_in,
                              void* d_out, int out_size){
    (void)in_sizes; (void)n_in; (void)out_size;
    const float* input = (const float*)d_in[0];
    const int*   seq   = (const int*)d_in[1];
    const float* eWih  = (const float*)d_in[2];
    const float* eWhh  = (const float*)d_in[3];
    const float* ebih  = (const float*)d_in[4];
    const float* ebhh  = (const float*)d_in[5];
    const float* dWih  = (const float*)d_in[6];
    const float* dWhh  = (const float*)d_in[7];
    const float* dbih  = (const float*)d_in[8];
    const float* dbhh  = (const float*)d_in[9];
    const float* Wout  = (const float*)d_in[10];
    const float* bo    = (const float*)d_in[11];
    float* out = (float*)d_out;

    cudaFuncSetAttribute(gru_ae_kernel, cudaFuncAttributeMaxDynamicSharedMemorySize, SMEMSZ);

    cudaMemcpyAsync(out + OFF_INP, input, (size_t)Bsz * Tn * sizeof(float),
                    cudaMemcpyDeviceToDevice, 0);
    gru_ae_kernel<<<NCTA, NTHR, SMEMSZ, 0>>>(input, seq, eWih, eWhh, ebih, ebhh,
                                             dWih, dWhh, dbih, dbhh, Wout, bo, out);
}